// round 1
// baseline (speedup 1.0000x reference)
#include <cuda_runtime.h>

#define HID 128
#define NS  12
#define PAD 132          // row pitch in floats: conflict-free both directions
#define NW  8            // warps per CTA
#define NB  4            // batch elements per warp-task
#define THREADS 256
#define GRID 148

// ---- shared memory layout (float offsets) ----
#define OW1   0                      // W1^T  [128][132]
#define OW2   16896                  // W2^T  [128][132]
#define OW0   33792                  // W0^T  [12][132]
#define OR3   35376                  // R3 = Wout*W3   [128]
#define OB0   35504
#define OB1   35632
#define OB2   35760
#define OCEN  35888                  // 12 (pad 16)
#define OINV  35904                  // 12 (pad 16)
#define OC3   35920                  // 1 (pad 4)
#define OWARP 35924
#define WSTRIDE 2112                 // XQ 64 + V0Q 512 + V1Q 512 + GA 512 + GB 512
#define SMEM_FLOATS (OWARP + NW*WSTRIDE)   // 52820 floats = 211280 B

__device__ float g_R3[HID];
__device__ float g_c3;

// Precompute R3 = Wout @ W3 (1x128) and c3 = Wout@b3 + bout. Batch-independent.
__global__ void init_kernel(const float* __restrict__ W3, const float* __restrict__ b3,
                            const float* __restrict__ Wout, const float* __restrict__ bout)
{
    int h = threadIdx.x;  // 0..127
    float acc = 0.f;
    for (int j = 0; j < HID; ++j) acc = fmaf(Wout[j], W3[j*HID + h], acc);
    g_R3[h] = acc;
    if (h == 0) {
        float c = bout[0];
        for (int j = 0; j < HID; ++j) c = fmaf(Wout[j], b3[j], c);
        g_c3 = c;
    }
}

// Fast tanh: 1 - 2/(e^{2x}+1). Safe at +/-inf, ~1e-6 rel err (MUFU EX2/RCP).
__device__ __forceinline__ float ftanh(float x)
{
    float e = __expf(2.0f * x);
    return 1.0f - __fdividef(2.0f, e + 1.0f);
}

// Forward matvec for 4 batches: z[j][p] = bias[4l+j] + sum_k Wt[k][4l+j] * in[k][p]
// Wt rows are PAD-pitched; in is interleaved [k][4].
template<int KN>
__device__ __forceinline__ void fwd_layer(const float* __restrict__ Wt,
                                          const float* __restrict__ bias,
                                          const float* __restrict__ inq,
                                          float z[4][4], int l)
{
    float4 bb = *(const float4*)&bias[4*l];
    float bj[4] = {bb.x, bb.y, bb.z, bb.w};
#pragma unroll
    for (int j = 0; j < 4; ++j)
#pragma unroll
        for (int p = 0; p < 4; ++p) z[j][p] = bj[j];

#pragma unroll 4
    for (int k = 0; k < KN; ++k) {
        float4 w4 = *(const float4*)&Wt[k*PAD + 4*l];   // lanes contiguous: conflict-free
        float4 x4 = *(const float4*)&inq[k*NB];         // broadcast: free
        float wj[4] = {w4.x, w4.y, w4.z, w4.w};
        float xp[4] = {x4.x, x4.y, x4.z, x4.w};
#pragma unroll
        for (int j = 0; j < 4; ++j)
#pragma unroll
            for (int p = 0; p < 4; ++p) z[j][p] = fmaf(wj[j], xp[p], z[j][p]);
    }
}

// Backward vecmat for 4 batches: r[m][p] = sum_h g[h][p] * Wt[(l+32m)][h]
// (Wt[k][h] = W[h][k], so this computes r = g . W)
__device__ __forceinline__ void bwd_layer(const float* __restrict__ Wt,
                                          const float* __restrict__ gin,
                                          float r[4][4], int l)
{
#pragma unroll
    for (int m = 0; m < 4; ++m)
#pragma unroll
        for (int p = 0; p < 4; ++p) r[m][p] = 0.f;

#pragma unroll 2
    for (int jj = 0; jj < 32; ++jj) {
        const float* gp = gin + 16*jj;
        float4 ga = *(const float4*)(gp);
        float4 gb = *(const float4*)(gp + 4);
        float4 gc = *(const float4*)(gp + 8);
        float4 gd = *(const float4*)(gp + 12);
        float g0[4] = {ga.x, ga.y, ga.z, ga.w};
        float g1[4] = {gb.x, gb.y, gb.z, gb.w};
        float g2[4] = {gc.x, gc.y, gc.z, gc.w};
        float g3[4] = {gd.x, gd.y, gd.z, gd.w};
#pragma unroll
        for (int m = 0; m < 4; ++m) {
            // lane stride 528B -> within each 8-lane phase, banks 4l..4l+3: conflict-free
            float4 w4 = *(const float4*)&Wt[(l + 32*m)*PAD + 4*jj];
#pragma unroll
            for (int p = 0; p < 4; ++p) {
                float acc = r[m][p];
                acc = fmaf(w4.x, g0[p], acc);
                acc = fmaf(w4.y, g1[p], acc);
                acc = fmaf(w4.z, g2[p], acc);
                acc = fmaf(w4.w, g3[p], acc);
                r[m][p] = acc;
            }
        }
    }
}

__global__ __launch_bounds__(THREADS, 1)
void mlp_kernel(const float* __restrict__ state,
                const float* __restrict__ safe_m, const float* __restrict__ safe_l,
                const float* __restrict__ W0, const float* __restrict__ b0,
                const float* __restrict__ W1, const float* __restrict__ b1,
                const float* __restrict__ W2, const float* __restrict__ b2,
                float* __restrict__ out, int nb)
{
    extern __shared__ float s[];
    int tid = threadIdx.x;

    // ---- stage weights into SMEM (transposed, padded) ----
    for (int i = tid; i < HID*HID; i += THREADS) {
        int h = i >> 7, k = i & 127;
        s[OW1 + k*PAD + h] = W1[i];
        s[OW2 + k*PAD + h] = W2[i];
    }
    for (int i = tid; i < HID*NS; i += THREADS) {
        int h = i / NS, k = i - h*NS;
        s[OW0 + k*PAD + h] = W0[i];
    }
    if (tid < HID) {
        s[OR3 + tid] = g_R3[tid];
        s[OB0 + tid] = b0[tid];
        s[OB1 + tid] = b1[tid];
        s[OB2 + tid] = b2[tid];
    }
    if (tid < NS) {
        float m = safe_m[tid], lo = safe_l[tid];
        s[OCEN + tid] = 0.5f * (m + lo);
        s[OINV + tid] = 2.0f / (m - lo);     // 1/x_range
    }
    if (tid == 0) s[OC3] = g_c3;
    __syncthreads();

    int w = tid >> 5, l = tid & 31;
    float* WB  = s + OWARP + w*WSTRIDE;
    float* XQ  = WB;           // [16][4]
    float* V0Q = WB + 64;      // [128][4]
    float* V1Q = WB + 576;     // [128][4]
    float* GA  = WB + 1088;    // [128][4]
    float* GB  = WB + 1600;    // [128][4]

    int quads = (nb + NB - 1) / NB;
    int gw = blockIdx.x * NW + w;
    int wt = gridDim.x * NW;

    for (int q = gw; q < quads; q += wt) {
        int base = q * NB;

        // A: load + normalize inputs, interleave 4 batches
        for (int i = l; i < NB*NS; i += 32) {
            int p = i / NS, k = i - p*NS;
            int bidx = base + p;
            float v = (bidx < nb) ? state[bidx*NS + k] : 0.f;
            XQ[k*NB + p] = (v - s[OCEN + k]) * s[OINV + k];
        }
        __syncwarp();

        float z[4][4];

        // B: input layer (K=12) + tanh
        fwd_layer<NS>(s + OW0, s + OB0, XQ, z, l);
#pragma unroll
        for (int j = 0; j < 4; ++j)
#pragma unroll
            for (int p = 0; p < 4; ++p)
                V0Q[(4*l + j)*NB + p] = ftanh(z[j][p]);
        __syncwarp();

        // C: layer 1 + tanh
        fwd_layer<HID>(s + OW1, s + OB1, V0Q, z, l);
#pragma unroll
        for (int j = 0; j < 4; ++j)
#pragma unroll
            for (int p = 0; p < 4; ++p)
                V1Q[(4*l + j)*NB + p] = ftanh(z[j][p]);
        __syncwarp();

        // D: layer 2 + tanh; g2 = R3 * (1 - V2^2); vout partial = R3 . V2
        fwd_layer<HID>(s + OW2, s + OB2, V1Q, z, l);
        {
            float vout[4] = {0.f, 0.f, 0.f, 0.f};
            float4 r4 = *(const float4*)&s[OR3 + 4*l];
            float rj[4] = {r4.x, r4.y, r4.z, r4.w};
#pragma unroll
            for (int j = 0; j < 4; ++j)
#pragma unroll
                for (int p = 0; p < 4; ++p) {
                    float t = ftanh(z[j][p]);
                    vout[p] = fmaf(rj[j], t, vout[p]);
                    GA[(4*l + j)*NB + p] = rj[j] * (1.f - t*t);
                }
#pragma unroll
            for (int p = 0; p < 4; ++p) {
                float v = vout[p];
#pragma unroll
                for (int off = 16; off > 0; off >>= 1)
                    v += __shfl_xor_sync(0xffffffffu, v, off);
                vout[p] = v;
            }
            if (l == 0) {
                float c3 = s[OC3];
#pragma unroll
                for (int p = 0; p < 4; ++p)
                    if (base + p < nb) out[(base + p)*13] = vout[p] + c3;
            }
        }
        __syncwarp();

        // E: r = g2 . W2 ; g1 = r * (1 - V1^2)
        float r[4][4];
        bwd_layer(s + OW2, GA, r, l);
#pragma unroll
        for (int m = 0; m < 4; ++m) {
            float4 v4 = *(const float4*)&V1Q[(l + 32*m)*NB];
            float vp[4] = {v4.x, v4.y, v4.z, v4.w};
#pragma unroll
            for (int p = 0; p < 4; ++p)
                GB[(l + 32*m)*NB + p] = r[m][p] * (1.f - vp[p]*vp[p]);
        }
        __syncwarp();

        // F: r = g1 . W1 ; g0 = r * (1 - V0^2)
        bwd_layer(s + OW1, GB, r, l);
#pragma unroll
        for (int m = 0; m < 4; ++m) {
            float4 v4 = *(const float4*)&V0Q[(l + 32*m)*NB];
            float vp[4] = {v4.x, v4.y, v4.z, v4.w};
#pragma unroll
            for (int p = 0; p < 4; ++p)
                GA[(l + 32*m)*NB + p] = r[m][p] * (1.f - vp[p]*vp[p]);
        }
        __syncwarp();

        // G: outJ[k] = (g0 . W0)[k] * invr[k]   (12 outputs, warp-reduced)
        {
            float pk[NS][4];
#pragma unroll
            for (int k = 0; k < NS; ++k)
#pragma unroll
                for (int p = 0; p < 4; ++p) pk[k][p] = 0.f;

#pragma unroll
            for (int j = 0; j < 4; ++j) {
                float4 g4 = *(const float4*)&GA[(4*l + j)*NB];
                float gp[4] = {g4.x, g4.y, g4.z, g4.w};
#pragma unroll
                for (int k = 0; k < NS; ++k) {
                    float wv = s[OW0 + k*PAD + 4*l + j];
#pragma unroll
                    for (int p = 0; p < 4; ++p)
                        pk[k][p] = fmaf(wv, gp[p], pk[k][p]);
                }
            }
#pragma unroll
            for (int k = 0; k < NS; ++k)
#pragma unroll
                for (int p = 0; p < 4; ++p) {
                    float v = pk[k][p];
#pragma unroll
                    for (int off = 16; off > 0; off >>= 1)
                        v += __shfl_xor_sync(0xffffffffu, v, off);
                    pk[k][p] = v;
                }
            if (l == 0) {
#pragma unroll
                for (int p = 0; p < 4; ++p)
                    if (base + p < nb) {
#pragma unroll
                        for (int k = 0; k < NS; ++k)
                            out[(base + p)*13 + 1 + k] = pk[k][p] * s[OINV + k];
                    }
            }
        }
        __syncwarp();
    }
}

extern "C" void kernel_launch(void* const* d_in, const int* in_sizes, int n_in,
                              void* d_out, int out_size)
{
    const float* state  = (const float*)d_in[0];
    const float* safe_m = (const float*)d_in[1];
    const float* safe_l = (const float*)d_in[2];
    const float* W0     = (const float*)d_in[3];
    const float* b0     = (const float*)d_in[4];
    const float* W1     = (const float*)d_in[5];
    const float* b1     = (const float*)d_in[6];
    const float* W2     = (const float*)d_in[7];
    const float* b2     = (const float*)d_in[8];
    const float* W3     = (const float*)d_in[9];
    const float* b3     = (const float*)d_in[10];
    const float* Wout   = (const float*)d_in[11];
    const float* bout   = (const float*)d_in[12];
    float* out = (float*)d_out;

    int nb = in_sizes[0] / NS;

    cudaFuncSetAttribute(mlp_kernel, cudaFuncAttributeMaxDynamicSharedMemorySize,
                         SMEM_FLOATS * (int)sizeof(float));

    init_kernel<<<1, HID>>>(W3, b3, Wout, bout);
    mlp_kernel<<<GRID, THREADS, SMEM_FLOATS * sizeof(float)>>>(
        state, safe_m, safe_l, W0, b0, W1, b1, W2, b2, out, nb);
}

// round 2
// speedup vs baseline: 1.2170x; 1.2170x over previous
#include <cuda_runtime.h>

#define HID 128
#define NS  12
#define PAD 132          // weight row pitch (floats): 4l-pattern conflict-free for bwd
#define NW  7            // warps per CTA
#define NB  8            // batch elements per warp-task
#define THREADS (NW*32)
#define GRID 148

typedef unsigned long long ull;

// ---- shared memory layout (float offsets) ----
#define OW1   0                      // W1^T  [128][132]  (Wt[k][h] = W[h][k])
#define OW2   16896                  // W2^T  [128][132]
#define OW0   33792                  // W0^T  [12][132]
#define OR3   35376                  // R3 = Wout*W3   [128]
#define OB0   35504
#define OB1   35632
#define OB2   35760
#define OCEN  35888                  // 12 (pad 16)
#define OINV  35904                  // 12 (pad 16)
#define OC3   35920                  // 1 (pad 4)
#define OWARP 35924
#define WSTRIDE 3072                 // V0 1024 + V1 1024 + G 1024 (XQ aliases G)
#define SMEM_FLOATS (OWARP + NW*WSTRIDE)   // 57428 floats = 229712 B  (< 232448)

__device__ float g_R3[HID];
__device__ float g_c3;

__global__ void init_kernel(const float* __restrict__ W3, const float* __restrict__ b3,
                            const float* __restrict__ Wout, const float* __restrict__ bout)
{
    int h = threadIdx.x;  // 0..127
    float acc = 0.f;
    for (int j = 0; j < HID; ++j) acc = fmaf(Wout[j], W3[j*HID + h], acc);
    g_R3[h] = acc;
    if (h == 0) {
        float c = bout[0];
        for (int j = 0; j < HID; ++j) c = fmaf(Wout[j], b3[j], c);
        g_c3 = c;
    }
}

// ---- packed f32x2 helpers ----
__device__ __forceinline__ ull ffma2(ull a, ull b, ull c)
{
    ull d;
    asm("fma.rn.f32x2 %0, %1, %2, %3;" : "=l"(d) : "l"(a), "l"(b), "l"(c));
    return d;
}
__device__ __forceinline__ ull pack2(float lo, float hi)
{
    ull d; asm("mov.b64 %0, {%1, %2};" : "=l"(d) : "f"(lo), "f"(hi)); return d;
}
__device__ __forceinline__ void unpack2(ull v, float& lo, float& hi)
{
    asm("mov.b64 {%0, %1}, %2;" : "=f"(lo), "=f"(hi) : "l"(v));
}

// Fast tanh: 1 - 2/(e^{2x}+1).
__device__ __forceinline__ float ftanh(float x)
{
    float e = __expf(2.0f * x);
    return 1.0f - __fdividef(2.0f, e + 1.0f);
}

// Forward matvec, 8 batches packed as 4 f32x2:
//   z[j][pp] (pair) = bias[4l+j] + sum_k Wt[k][4l+j] * in[k][pair pp]
template<int KN>
__device__ __forceinline__ void fwd2(const float* __restrict__ Wt,
                                     const float* __restrict__ bias,
                                     const float* __restrict__ inq,
                                     ull z[4][4], int l)
{
    float4 bb = *(const float4*)&bias[4*l];
    float bj[4] = {bb.x, bb.y, bb.z, bb.w};
#pragma unroll
    for (int j = 0; j < 4; ++j) {
        ull b2 = pack2(bj[j], bj[j]);
#pragma unroll
        for (int pp = 0; pp < 4; ++pp) z[j][pp] = b2;
    }

#pragma unroll 2
    for (int k = 0; k < KN; ++k) {
        float4 w4 = *(const float4*)&Wt[k*PAD + 4*l];       // lanes contiguous: conflict-free
        ulonglong2 xa = *(const ulonglong2*)&inq[k*NB];     // broadcast pairs (p0,p1),(p2,p3)
        ulonglong2 xb = *(const ulonglong2*)&inq[k*NB + 4];
        ull x[4] = {xa.x, xa.y, xb.x, xb.y};
        float wj[4] = {w4.x, w4.y, w4.z, w4.w};
#pragma unroll
        for (int j = 0; j < 4; ++j) {
            ull w2 = pack2(wj[j], wj[j]);
#pragma unroll
            for (int pp = 0; pp < 4; ++pp)
                z[j][pp] = ffma2(w2, x[pp], z[j][pp]);
        }
    }
}

// Backward vecmat, packed: r[m][pp] = sum_so g[so][pp] * Wt[(l+32m)][so]
__device__ __forceinline__ void bwd2(const float* __restrict__ Wt,
                                     const float* __restrict__ gin,
                                     ull r[4][4], int l)
{
#pragma unroll
    for (int m = 0; m < 4; ++m)
#pragma unroll
        for (int pp = 0; pp < 4; ++pp) r[m][pp] = 0ull;

#pragma unroll 2
    for (int c = 0; c < 32; ++c) {          // chunks of 4 so
        const float* gp = gin + c*4*NB;
        ull g[4][4];
#pragma unroll
        for (int s = 0; s < 4; ++s) {
            ulonglong2 ga = *(const ulonglong2*)(gp + s*NB);      // broadcast
            ulonglong2 gb = *(const ulonglong2*)(gp + s*NB + 4);
            g[s][0] = ga.x; g[s][1] = ga.y; g[s][2] = gb.x; g[s][3] = gb.y;
        }
#pragma unroll
        for (int m = 0; m < 4; ++m) {
            float4 w4 = *(const float4*)&Wt[(l + 32*m)*PAD + 4*c];  // 4l-pattern: conflict-free
            float wm[4] = {w4.x, w4.y, w4.z, w4.w};
#pragma unroll
            for (int s = 0; s < 4; ++s) {
                ull w2 = pack2(wm[s], wm[s]);
#pragma unroll
                for (int pp = 0; pp < 4; ++pp)
                    r[m][pp] = ffma2(w2, g[s][pp], r[m][pp]);
            }
        }
    }
}

__global__ __launch_bounds__(THREADS, 1)
void mlp_kernel(const float* __restrict__ state,
                const float* __restrict__ safe_m, const float* __restrict__ safe_l,
                const float* __restrict__ W0, const float* __restrict__ b0,
                const float* __restrict__ W1, const float* __restrict__ b1,
                const float* __restrict__ W2, const float* __restrict__ b2,
                float* __restrict__ out, int nb)
{
    extern __shared__ float s[];
    int tid = threadIdx.x;

    // ---- stage weights into SMEM (transposed, PAD-pitched) ----
    for (int i = tid; i < HID*HID; i += THREADS) {
        int h = i >> 7, k = i & 127;
        s[OW1 + k*PAD + h] = W1[i];
        s[OW2 + k*PAD + h] = W2[i];
    }
    for (int i = tid; i < HID*NS; i += THREADS) {
        int h = i / NS, k = i - h*NS;
        s[OW0 + k*PAD + h] = W0[i];
    }
    if (tid < HID) {
        s[OR3 + tid] = g_R3[tid];
        s[OB0 + tid] = b0[tid];
        s[OB1 + tid] = b1[tid];
        s[OB2 + tid] = b2[tid];
    }
    if (tid < NS) {
        float m = safe_m[tid], lo = safe_l[tid];
        s[OCEN + tid] = 0.5f * (m + lo);
        s[OINV + tid] = 2.0f / (m - lo);
    }
    if (tid == 0) s[OC3] = g_c3;
    __syncthreads();

    int w = tid >> 5, l = tid & 31;
    float* WB = s + OWARP + w*WSTRIDE;
    float* V0 = WB;            // [128][8]
    float* V1 = WB + 1024;     // [128][8]
    float* G  = WB + 2048;     // [128][8]; XQ [12][8] aliases the front
    float* XQ = G;

    int quads = (nb + NB - 1) / NB;
    int gw = blockIdx.x * NW + w;
    int wt = GRID * NW;

    for (int q = gw; q < quads; q += wt) {
        int base = q * NB;

        // ---- A: load + normalize inputs, interleaved [k][p] ----
        for (int i = l; i < NB*NS; i += 32) {
            int k = i >> 3, p = i & 7;
            int bidx = base + p;
            float v = (bidx < nb) ? state[bidx*NS + k] : 0.f;
            XQ[k*NB + p] = (v - s[OCEN + k]) * s[OINV + k];
        }
        __syncwarp();

        ull z[4][4];
        float t[8];

        // ---- B: input layer (K=12) + tanh -> V0 ----
        fwd2<NS>(s + OW0, s + OB0, XQ, z, l);
#pragma unroll
        for (int j = 0; j < 4; ++j) {
#pragma unroll
            for (int pp = 0; pp < 4; ++pp) {
                unpack2(z[j][pp], t[2*pp], t[2*pp+1]);
            }
#pragma unroll
            for (int p = 0; p < 8; ++p) t[p] = ftanh(t[p]);
            *(float4*)&V0[(4*l + j)*NB]     = make_float4(t[0], t[1], t[2], t[3]);
            *(float4*)&V0[(4*l + j)*NB + 4] = make_float4(t[4], t[5], t[6], t[7]);
        }
        __syncwarp();

        // ---- C: layer 1 + tanh -> V1 ----
        fwd2<HID>(s + OW1, s + OB1, V0, z, l);
#pragma unroll
        for (int j = 0; j < 4; ++j) {
#pragma unroll
            for (int pp = 0; pp < 4; ++pp) {
                unpack2(z[j][pp], t[2*pp], t[2*pp+1]);
            }
#pragma unroll
            for (int p = 0; p < 8; ++p) t[p] = ftanh(t[p]);
            *(float4*)&V1[(4*l + j)*NB]     = make_float4(t[0], t[1], t[2], t[3]);
            *(float4*)&V1[(4*l + j)*NB + 4] = make_float4(t[4], t[5], t[6], t[7]);
        }
        __syncwarp();

        // ---- D: layer 2 + tanh; vout partial = R3.V2 ; g2 = R3*(1-V2^2) -> G ----
        fwd2<HID>(s + OW2, s + OB2, V1, z, l);
        float vout[8];
        {
            ull vo[4] = {0ull, 0ull, 0ull, 0ull};
            float4 r4 = *(const float4*)&s[OR3 + 4*l];
            float rj[4] = {r4.x, r4.y, r4.z, r4.w};
#pragma unroll
            for (int j = 0; j < 4; ++j) {
                ull rj2 = pack2(rj[j], rj[j]);
#pragma unroll
                for (int pp = 0; pp < 4; ++pp) {
                    unpack2(z[j][pp], t[2*pp], t[2*pp+1]);
                }
#pragma unroll
                for (int p = 0; p < 8; ++p) t[p] = ftanh(t[p]);
#pragma unroll
                for (int pp = 0; pp < 4; ++pp)
                    vo[pp] = ffma2(rj2, pack2(t[2*pp], t[2*pp+1]), vo[pp]);
                float gq[8];
#pragma unroll
                for (int p = 0; p < 8; ++p) gq[p] = rj[j] * (1.f - t[p]*t[p]);
                *(float4*)&G[(4*l + j)*NB]     = make_float4(gq[0], gq[1], gq[2], gq[3]);
                *(float4*)&G[(4*l + j)*NB + 4] = make_float4(gq[4], gq[5], gq[6], gq[7]);
            }
#pragma unroll
            for (int pp = 0; pp < 4; ++pp)
                unpack2(vo[pp], vout[2*pp], vout[2*pp+1]);
#pragma unroll
            for (int p = 0; p < 8; ++p) {
                float v = vout[p];
#pragma unroll
                for (int off = 16; off > 0; off >>= 1)
                    v += __shfl_xor_sync(0xffffffffu, v, off);
                vout[p] = v;
            }
        }
        __syncwarp();

        ull r[4][4];

        // ---- E: r = g2.W2 ; g1 = r*(1-V1^2) -> G (aliased; sync guards ITS) ----
        bwd2(s + OW2, G, r, l);
        __syncwarp();
#pragma unroll
        for (int m = 0; m < 4; ++m) {
            const float* vp = &V1[(l + 32*m)*NB];
            float gq[8];
#pragma unroll
            for (int pp = 0; pp < 4; ++pp) {
                float r0, r1; unpack2(r[m][pp], r0, r1);
                float v0 = vp[2*pp], v1 = vp[2*pp+1];
                gq[2*pp]   = r0 * (1.f - v0*v0);
                gq[2*pp+1] = r1 * (1.f - v1*v1);
            }
            *(float4*)&G[(l + 32*m)*NB]     = make_float4(gq[0], gq[1], gq[2], gq[3]);
            *(float4*)&G[(l + 32*m)*NB + 4] = make_float4(gq[4], gq[5], gq[6], gq[7]);
        }
        __syncwarp();

        // ---- F: r = g1.W1 ; g0 = r*(1-V0^2) -> G ----
        bwd2(s + OW1, G, r, l);
        __syncwarp();
#pragma unroll
        for (int m = 0; m < 4; ++m) {
            const float* vp = &V0[(l + 32*m)*NB];
            float gq[8];
#pragma unroll
            for (int pp = 0; pp < 4; ++pp) {
                float r0, r1; unpack2(r[m][pp], r0, r1);
                float v0 = vp[2*pp], v1 = vp[2*pp+1];
                gq[2*pp]   = r0 * (1.f - v0*v0);
                gq[2*pp+1] = r1 * (1.f - v1*v1);
            }
            *(float4*)&G[(l + 32*m)*NB]     = make_float4(gq[0], gq[1], gq[2], gq[3]);
            *(float4*)&G[(l + 32*m)*NB + 4] = make_float4(gq[4], gq[5], gq[6], gq[7]);
        }
        __syncwarp();

        // ---- G: each lane owns 3 (k,p) outputs: flat = l+32c ; J[k][p] = sum_h g0[h][p]*W0t[k][h]
        {
            int p  = l & 7;
            int k0 = l >> 3;            // k for c: k0 + 4c
            float acc[3] = {0.f, 0.f, 0.f};
#pragma unroll 4
            for (int h = 0; h < HID; ++h) {
                float gv = G[h*NB + p];
#pragma unroll
                for (int c = 0; c < 3; ++c)
                    acc[c] = fmaf(gv, s[OW0 + (k0 + 4*c)*PAD + h], acc[c]);
            }
            // V output (all lanes hold all 8 reduced vout values)
            if (l < NB && base + l < nb)
                out[(base + l)*13] = vout[l] + s[OC3];
            if (base + p < nb) {
#pragma unroll
                for (int c = 0; c < 3; ++c) {
                    int k = k0 + 4*c;
                    out[(base + p)*13 + 1 + k] = acc[c] * s[OINV + k];
                }
            }
        }
        __syncwarp();
    }
}

extern "C" void kernel_launch(void* const* d_in, const int* in_sizes, int n_in,
                              void* d_out, int out_size)
{
    const float* state  = (const float*)d_in[0];
    const float* safe_m = (const float*)d_in[1];
    const float* safe_l = (const float*)d_in[2];
    const float* W0     = (const float*)d_in[3];
    const float* b0     = (const float*)d_in[4];
    const float* W1     = (const float*)d_in[5];
    const float* b1     = (const float*)d_in[6];
    const float* W2     = (const float*)d_in[7];
    const float* b2     = (const float*)d_in[8];
    const float* W3     = (const float*)d_in[9];
    const float* b3     = (const float*)d_in[10];
    const float* Wout   = (const float*)d_in[11];
    const float* bout   = (const float*)d_in[12];
    float* out = (float*)d_out;

    int nb = in_sizes[0] / NS;

    cudaFuncSetAttribute(mlp_kernel, cudaFuncAttributeMaxDynamicSharedMemorySize,
                         SMEM_FLOATS * (int)sizeof(float));

    init_kernel<<<1, HID>>>(W3, b3, Wout, bout);
    mlp_kernel<<<GRID, THREADS, SMEM_FLOATS * sizeof(float)>>>(
        state, safe_m, safe_l, W0, b0, W1, b1, W2, b2, out, nb);
}

// round 3
// speedup vs baseline: 1.2207x; 1.0030x over previous
#include <cuda_runtime.h>

#define HID 128
#define NS  12
#define PAD 132          // weight row pitch (floats)
#define NW  10           // warps per CTA
#define NB  8            // batch elements per warp-task
#define THREADS (NW*32)
#define GRID 148

typedef unsigned long long ull;

// ---- shared memory layout (float offsets) ----
#define OW1   0                      // W1^T  [128][132]  (Wt[k][h] = W[h][k])
#define OW2   16896                  // W2^T  [128][132]
#define OW0   33792                  // W0^T  [12][132]
#define OR3   35376                  // R3 = Wout*W3   [128]
#define OB0   35504
#define OB1   35632
#define OB2   35760
#define OCEN  35888                  // 12 (pad 16)
#define OINV  35904                  // 12 (pad 16)
#define OC3   35920                  // 1 (pad 8 -> align warp region to 32B)
#define OWARP 35928                  // 32B aligned (35928*4 % 32 == 0)
#define WSTRIDE 2176                 // G/V0 1024 + V1 1024 + XQ 128
#define SMEM_FLOATS (OWARP + NW*WSTRIDE)   // 57688 floats = 230752 B (< 232448)

__device__ float g_R3[HID];
__device__ float g_c3;

__global__ void init_kernel(const float* __restrict__ W3, const float* __restrict__ b3,
                            const float* __restrict__ Wout, const float* __restrict__ bout)
{
    int h = threadIdx.x;  // 0..127
    float acc = 0.f;
    for (int j = 0; j < HID; ++j) acc = fmaf(Wout[j], W3[j*HID + h], acc);
    g_R3[h] = acc;
    if (h == 0) {
        float c = bout[0];
        for (int j = 0; j < HID; ++j) c = fmaf(Wout[j], b3[j], c);
        g_c3 = c;
    }
}

// ---- packed f32x2 helpers ----
__device__ __forceinline__ ull ffma2(ull a, ull b, ull c)
{
    ull d;
    asm("fma.rn.f32x2 %0, %1, %2, %3;" : "=l"(d) : "l"(a), "l"(b), "l"(c));
    return d;
}
__device__ __forceinline__ ull pack2(float lo, float hi)
{
    ull d; asm("mov.b64 %0, {%1, %2};" : "=l"(d) : "f"(lo), "f"(hi)); return d;
}
__device__ __forceinline__ void unpack2(ull v, float& lo, float& hi)
{
    asm("mov.b64 {%0, %1}, %2;" : "=f"(lo), "=f"(hi) : "l"(v));
}

// Fast tanh: 1 - 2/(e^{2x}+1).
__device__ __forceinline__ float ftanh(float x)
{
    float e = __expf(2.0f * x);
    return 1.0f - __fdividef(2.0f, e + 1.0f);
}

// ---- bank swizzle for [128][8] scratch rows (32B rows) ----
// physical row: low 2 bits XORed with bits [3:2]; chunk-swap bit from bits 2^4.
__device__ __forceinline__ int physrow(int h) { return (h & ~3) | ((h ^ (h >> 2)) & 3); }
__device__ __forceinline__ int cswap(int h)   { return ((h >> 2) ^ (h >> 4)) & 1; }

// Store one row (8 floats, batches p0..p7) swizzled. Conflict-free for both
// h=4l+j (fwd) and h=l+32m (bwd) lane patterns.
__device__ __forceinline__ void store8(float* buf, int h, const float t[8])
{
    float* rp = buf + physrow(h)*8;
    int b = cswap(h);
    *(float4*)(rp + 4*b)     = make_float4(t[0], t[1], t[2], t[3]);
    *(float4*)(rp + 4*(b^1)) = make_float4(t[4], t[5], t[6], t[7]);
}
// Load one row into 4 broadcast pairs.
__device__ __forceinline__ void load4p(const float* buf, int h, ull x[4])
{
    const float* rp = buf + physrow(h)*8;
    int b = cswap(h);
    ulonglong2 xa = *(const ulonglong2*)(rp + 4*b);      // pairs 0,1
    ulonglong2 xb = *(const ulonglong2*)(rp + 4*(b^1));  // pairs 2,3
    x[0] = xa.x; x[1] = xa.y; x[2] = xb.x; x[3] = xb.y;
}
// Load one row as 8 floats.
__device__ __forceinline__ void load8(const float* buf, int h, float t[8])
{
    const float* rp = buf + physrow(h)*8;
    int b = cswap(h);
    float4 va = *(const float4*)(rp + 4*b);
    float4 vb = *(const float4*)(rp + 4*(b^1));
    t[0]=va.x; t[1]=va.y; t[2]=va.z; t[3]=va.w;
    t[4]=vb.x; t[5]=vb.y; t[6]=vb.z; t[7]=vb.w;
}

// Forward matvec, 8 batches packed as 4 f32x2:
//   z[j][pp] = bias[4l+j] + sum_k Wt[k][4l+j] * in[k][pair pp]
template<int KN>
__device__ __forceinline__ void fwd2(const float* __restrict__ Wt,
                                     const float* __restrict__ bias,
                                     const float* __restrict__ inq,
                                     ull z[4][4], int l)
{
    float4 bb = *(const float4*)&bias[4*l];
    float bj[4] = {bb.x, bb.y, bb.z, bb.w};
#pragma unroll
    for (int j = 0; j < 4; ++j) {
        ull b2 = pack2(bj[j], bj[j]);
#pragma unroll
        for (int pp = 0; pp < 4; ++pp) z[j][pp] = b2;
    }

#pragma unroll 4
    for (int k = 0; k < KN; ++k) {
        float4 w4 = *(const float4*)&Wt[k*PAD + 4*l];   // 128B contiguous: 4 wf
        ull x[4];
        load4p(inq, k, x);                              // 2 broadcasts
        float wj[4] = {w4.x, w4.y, w4.z, w4.w};
#pragma unroll
        for (int j = 0; j < 4; ++j) {
            ull w2 = pack2(wj[j], wj[j]);
#pragma unroll
            for (int pp = 0; pp < 4; ++pp)
                z[j][pp] = ffma2(w2, x[pp], z[j][pp]);
        }
    }
}

// Backward vecmat: r[m][pp] = sum_h g[h][pp] * Wt[(l+32m)][h]
__device__ __forceinline__ void bwd2(const float* __restrict__ Wt,
                                     const float* __restrict__ gin,
                                     ull r[4][4], int l)
{
#pragma unroll
    for (int m = 0; m < 4; ++m)
#pragma unroll
        for (int pp = 0; pp < 4; ++pp) r[m][pp] = 0ull;

#pragma unroll 2
    for (int c = 0; c < 32; ++c) {          // chunks of 4 h-rows
        int perm = c & 3, b = (c ^ (c >> 2)) & 1;
        ull g[4][4];
#pragma unroll
        for (int s = 0; s < 4; ++s) {
            const float* rp = gin + (4*c + (s ^ perm))*8;   // = physrow(4c+s)
            ulonglong2 ga = *(const ulonglong2*)(rp + 4*b);
            ulonglong2 gb = *(const ulonglong2*)(rp + 4*(b^1));
            g[s][0] = ga.x; g[s][1] = ga.y; g[s][2] = gb.x; g[s][3] = gb.y;
        }
#pragma unroll
        for (int m = 0; m < 4; ++m) {
            float4 w4 = *(const float4*)&Wt[(l + 32*m)*PAD + 4*c]; // phase-conflict-free
            float wm[4] = {w4.x, w4.y, w4.z, w4.w};
#pragma unroll
            for (int s = 0; s < 4; ++s) {
                ull w2 = pack2(wm[s], wm[s]);
#pragma unroll
                for (int pp = 0; pp < 4; ++pp)
                    r[m][pp] = ffma2(w2, g[s][pp], r[m][pp]);
            }
        }
    }
}

__global__ __launch_bounds__(THREADS, 1)
void mlp_kernel(const float* __restrict__ state,
                const float* __restrict__ safe_m, const float* __restrict__ safe_l,
                const float* __restrict__ W0, const float* __restrict__ b0,
                const float* __restrict__ W1, const float* __restrict__ b1,
                const float* __restrict__ W2, const float* __restrict__ b2,
                float* __restrict__ out, int nb)
{
    extern __shared__ float s[];
    int tid = threadIdx.x;

    // ---- stage weights into SMEM (transposed, PAD-pitched) ----
    for (int i = tid; i < HID*HID; i += THREADS) {
        int h = i >> 7, k = i & 127;
        s[OW1 + k*PAD + h] = W1[i];
        s[OW2 + k*PAD + h] = W2[i];
    }
    for (int i = tid; i < HID*NS; i += THREADS) {
        int h = i / NS, k = i - h*NS;
        s[OW0 + k*PAD + h] = W0[i];
    }
    if (tid < HID) {
        s[OR3 + tid] = g_R3[tid];
        s[OB0 + tid] = b0[tid];
        s[OB1 + tid] = b1[tid];
        s[OB2 + tid] = b2[tid];
    }
    if (tid < NS) {
        float m = safe_m[tid], lo = safe_l[tid];
        s[OCEN + tid] = 0.5f * (m + lo);
        s[OINV + tid] = 2.0f / (m - lo);
    }
    if (tid == 0) s[OC3] = g_c3;
    __syncthreads();

    int w = tid >> 5, l = tid & 31;
    float* WB = s + OWARP + w*WSTRIDE;
    float* G  = WB;            // [128][8] swizzled; holds V0 (B..C), then g2/g1/g0
    float* V1 = WB + 1024;     // [128][8] swizzled
    float* XQ = WB + 2048;     // [12][8]  swizzled (rows < 16 -> cswap=...)

    int quads = (nb + NB - 1) / NB;
    int gw = blockIdx.x + GRID * w;     // warp-major: balances tasks per SM
    int wt = GRID * NW;

    for (int q = gw; q < quads; q += wt) {
        int base = q * NB;

        // ---- A: load + normalize inputs (swizzled scalar writes) ----
        for (int i = l; i < NB*NS; i += 32) {
            int k = i >> 3, p = i & 7;
            int bidx = base + p;
            float v = (bidx < nb) ? state[bidx*NS + k] : 0.f;
            XQ[physrow(k)*8 + 4*((p>>2) ^ cswap(k)) + (p&3)] =
                (v - s[OCEN + k]) * s[OINV + k];
        }
        __syncwarp();

        ull z[4][4];
        float t[8];

        // ---- B: input layer (K=12) + tanh -> V0 (in G buffer) ----
        fwd2<NS>(s + OW0, s + OB0, XQ, z, l);
#pragma unroll
        for (int j = 0; j < 4; ++j) {
#pragma unroll
            for (int pp = 0; pp < 4; ++pp) unpack2(z[j][pp], t[2*pp], t[2*pp+1]);
#pragma unroll
            for (int p = 0; p < 8; ++p) t[p] = ftanh(t[p]);
            store8(G, 4*l + j, t);
        }
        __syncwarp();

        // ---- C: layer 1 + tanh -> V1 (reads V0 from G) ----
        fwd2<HID>(s + OW1, s + OB1, G, z, l);
#pragma unroll
        for (int j = 0; j < 4; ++j) {
#pragma unroll
            for (int pp = 0; pp < 4; ++pp) unpack2(z[j][pp], t[2*pp], t[2*pp+1]);
#pragma unroll
            for (int p = 0; p < 8; ++p) t[p] = ftanh(t[p]);
            store8(V1, 4*l + j, t);
        }
        __syncwarp();

        // ---- D: layer 2 + tanh; vout = R3.V2 ; g2 = R3*(1-V2^2) -> G ----
        fwd2<HID>(s + OW2, s + OB2, V1, z, l);
        float vout[8];
        {
            ull vo[4] = {0ull, 0ull, 0ull, 0ull};
            float4 r4 = *(const float4*)&s[OR3 + 4*l];
            float rj[4] = {r4.x, r4.y, r4.z, r4.w};
#pragma unroll
            for (int j = 0; j < 4; ++j) {
                ull rj2 = pack2(rj[j], rj[j]);
#pragma unroll
                for (int pp = 0; pp < 4; ++pp) unpack2(z[j][pp], t[2*pp], t[2*pp+1]);
#pragma unroll
                for (int p = 0; p < 8; ++p) t[p] = ftanh(t[p]);
#pragma unroll
                for (int pp = 0; pp < 4; ++pp)
                    vo[pp] = ffma2(rj2, pack2(t[2*pp], t[2*pp+1]), vo[pp]);
                float gq[8];
#pragma unroll
                for (int p = 0; p < 8; ++p) gq[p] = rj[j] * (1.f - t[p]*t[p]);
                store8(G, 4*l + j, gq);
            }
#pragma unroll
            for (int pp = 0; pp < 4; ++pp) unpack2(vo[pp], vout[2*pp], vout[2*pp+1]);
#pragma unroll
            for (int p = 0; p < 8; ++p) {
                float v = vout[p];
#pragma unroll
                for (int off = 16; off > 0; off >>= 1)
                    v += __shfl_xor_sync(0xffffffffu, v, off);
                vout[p] = v;
            }
        }
        __syncwarp();

        ull r[4][4];

        // ---- E: r = g2.W2 ; g1 = r*(1-V1^2) -> G ----
        bwd2(s + OW2, G, r, l);
        __syncwarp();
#pragma unroll
        for (int m = 0; m < 4; ++m) {
            float vp[8];
            load8(V1, l + 32*m, vp);
            float gq[8];
#pragma unroll
            for (int pp = 0; pp < 4; ++pp) {
                float r0, r1; unpack2(r[m][pp], r0, r1);
                gq[2*pp]   = r0 * (1.f - vp[2*pp]*vp[2*pp]);
                gq[2*pp+1] = r1 * (1.f - vp[2*pp+1]*vp[2*pp+1]);
            }
            store8(G, l + 32*m, gq);
        }
        __syncwarp();

        // ---- F: recompute s0 = 1-V0^2 for rows l+32m from XQ (registers), then
        //         r = g1.W1 ; g0 = r*s0 -> G ----
        float s0[4][8];
        {
            ull z0[4][4];
            float4 b4;
#pragma unroll
            for (int m = 0; m < 4; ++m) {
                float bm = s[OB0 + l + 32*m];
                ull b2 = pack2(bm, bm);
#pragma unroll
                for (int pp = 0; pp < 4; ++pp) z0[m][pp] = b2;
            }
            (void)b4;
#pragma unroll
            for (int k = 0; k < NS; ++k) {
                ull x[4];
                load4p(XQ, k, x);
#pragma unroll
                for (int m = 0; m < 4; ++m) {
                    float wv = s[OW0 + k*PAD + l + 32*m];
                    ull w2 = pack2(wv, wv);
#pragma unroll
                    for (int pp = 0; pp < 4; ++pp)
                        z0[m][pp] = ffma2(w2, x[pp], z0[m][pp]);
                }
            }
#pragma unroll
            for (int m = 0; m < 4; ++m)
#pragma unroll
                for (int pp = 0; pp < 4; ++pp) {
                    float a, b; unpack2(z0[m][pp], a, b);
                    a = ftanh(a); b = ftanh(b);
                    s0[m][2*pp]   = 1.f - a*a;
                    s0[m][2*pp+1] = 1.f - b*b;
                }
        }
        bwd2(s + OW1, G, r, l);
        __syncwarp();
#pragma unroll
        for (int m = 0; m < 4; ++m) {
            float gq[8];
#pragma unroll
            for (int pp = 0; pp < 4; ++pp) {
                float r0, r1; unpack2(r[m][pp], r0, r1);
                gq[2*pp]   = r0 * s0[m][2*pp];
                gq[2*pp+1] = r1 * s0[m][2*pp+1];
            }
            store8(G, l + 32*m, gq);
        }
        __syncwarp();

        // ---- final: J[k][p] = (sum_h g0[h][p] * W0t[k][h]) * inv[k] ----
        {
            int p  = l & 7;
            int k0 = l >> 3;                 // k = k0 + 4c, c in 0..2
            int psel = p >> 2, pw = p & 3;
            float acc[3] = {0.f, 0.f, 0.f};
#pragma unroll 2
            for (int i = 0; i < 32; ++i) {   // h = 4i..4i+3
                float4 w0 = *(const float4*)&s[OW0 + (k0    )*PAD + 4*i];
                float4 w1 = *(const float4*)&s[OW0 + (k0 + 4)*PAD + 4*i];
                float4 w2 = *(const float4*)&s[OW0 + (k0 + 8)*PAD + 4*i];
                float gv[4];
#pragma unroll
                for (int d = 0; d < 4; ++d) {
                    int h = 4*i + d;
                    gv[d] = G[physrow(h)*8 + 4*(psel ^ cswap(h)) + pw];
                }
                acc[0] = fmaf(w0.x, gv[0], acc[0]); acc[0] = fmaf(w0.y, gv[1], acc[0]);
                acc[0] = fmaf(w0.z, gv[2], acc[0]); acc[0] = fmaf(w0.w, gv[3], acc[0]);
                acc[1] = fmaf(w1.x, gv[0], acc[1]); acc[1] = fmaf(w1.y, gv[1], acc[1]);
                acc[1] = fmaf(w1.z, gv[2], acc[1]); acc[1] = fmaf(w1.w, gv[3], acc[1]);
                acc[2] = fmaf(w2.x, gv[0], acc[2]); acc[2] = fmaf(w2.y, gv[1], acc[2]);
                acc[2] = fmaf(w2.z, gv[2], acc[2]); acc[2] = fmaf(w2.w, gv[3], acc[2]);
            }
            if (l < NB && base + l < nb)
                out[(base + l)*13] = vout[l] + s[OC3];
            if (base + p < nb) {
#pragma unroll
                for (int c = 0; c < 3; ++c) {
                    int k = k0 + 4*c;
                    out[(base + p)*13 + 1 + k] = acc[c] * s[OINV + k];
                }
            }
        }
        __syncwarp();
    }
}

extern "C" void kernel_launch(void* const* d_in, const int* in_sizes, int n_in,
                              void* d_out, int out_size)
{
    const float* state  = (const float*)d_in[0];
    const float* safe_m = (const float*)d_in[1];
    const float* safe_l = (const float*)d_in[2];
    const float* W0     = (const float*)d_in[3];
    const float* b0     = (const float*)d_in[4];
    const float* W1     = (const float*)d_in[5];
    const float* b1     = (const float*)d_in[6];
    const float* W2     = (const float*)d_in[7];
    const float* b2     = (const float*)d_in[8];
    const float* W3     = (const float*)d_in[9];
    const float* b3     = (const float*)d_in[10];
    const float* Wout   = (const float*)d_in[11];
    const float* bout   = (const float*)d_in[12];
    float* out = (float*)d_out;

    int nb = in_sizes[0] / NS;

    cudaFuncSetAttribute(mlp_kernel, cudaFuncAttributeMaxDynamicSharedMemorySize,
                         SMEM_FLOATS * (int)sizeof(float));

    init_kernel<<<1, HID>>>(W3, b3, Wout, bout);
    mlp_kernel<<<GRID, THREADS, SMEM_FLOATS * sizeof(float)>>>(
        state, safe_m, safe_l, W0, b0, W1, b1, W2, b2, out, nb);
}

// round 4
// speedup vs baseline: 1.3265x; 1.0867x over previous
#include <cuda_runtime.h>
#include <cuda_fp16.h>

#define HID 128
#define NS  12
#define PAD 132          // weight row pitch (floats)
#define NW  14           // warps per CTA
#define NB  8            // batch elements per warp-task
#define THREADS (NW*32)
#define GRID 148

typedef unsigned long long ull;

// ---- shared memory layout (float offsets) ----
#define OW1   0                      // W1^T  [128][132]  (Wt[k][h] = W[h][k])
#define OW2   16896                  // W2^T  [128][132]
#define OW0   33792                  // W0^T  [12][132]
#define OCEN  35376                  // 12 (pad 16)
#define OINV  35392                  // 12 (pad 16)
#define OWARP 35408                  // 32B aligned
#define WSTRIDE 1536                 // BigA 1024 + V1h 512
#define SMEM_FLOATS (OWARP + NW*WSTRIDE)   // 56912 floats = 227648 B

__device__ float g_R3[HID];
__device__ float g_c3;

__global__ void init_kernel(const float* __restrict__ W3, const float* __restrict__ b3,
                            const float* __restrict__ Wout, const float* __restrict__ bout)
{
    int h = threadIdx.x;  // 0..127
    float acc = 0.f;
    for (int j = 0; j < HID; ++j) acc = fmaf(Wout[j], W3[j*HID + h], acc);
    g_R3[h] = acc;
    if (h == 0) {
        float c = bout[0];
        for (int j = 0; j < HID; ++j) c = fmaf(Wout[j], b3[j], c);
        g_c3 = c;
    }
}

// ---- packed f32x2 helpers ----
__device__ __forceinline__ ull ffma2(ull a, ull b, ull c)
{
    ull d;
    asm("fma.rn.f32x2 %0, %1, %2, %3;" : "=l"(d) : "l"(a), "l"(b), "l"(c));
    return d;
}
__device__ __forceinline__ ull pack2(float lo, float hi)
{
    ull d; asm("mov.b64 %0, {%1, %2};" : "=l"(d) : "f"(lo), "f"(hi)); return d;
}
__device__ __forceinline__ void unpack2(ull v, float& lo, float& hi)
{
    asm("mov.b64 {%0, %1}, %2;" : "=f"(lo), "=f"(hi) : "l"(v));
}
__device__ __forceinline__ ull shflx(ull v, int src)
{
    return __shfl_sync(0xffffffffu, v, src);
}

// Fast tanh: 1 - 2/(e^{2x}+1).
__device__ __forceinline__ float ftanh(float x)
{
    float e = __expf(2.0f * x);
    return 1.0f - __fdividef(2.0f, e + 1.0f);
}

// ---- bank swizzle for BigA [128][8] fp32 rows (32B rows) ----
__device__ __forceinline__ int physrow(int h) { return (h & ~3) | ((h ^ (h >> 2)) & 3); }
__device__ __forceinline__ int cswap(int h)   { return ((h >> 2) ^ (h >> 4)) & 1; }

__device__ __forceinline__ void store8(float* buf, int h, const float t[8])
{
    float* rp = buf + physrow(h)*8;
    int b = cswap(h);
    *(float4*)(rp + 4*b)     = make_float4(t[0], t[1], t[2], t[3]);
    *(float4*)(rp + 4*(b^1)) = make_float4(t[4], t[5], t[6], t[7]);
}

// ---- fp16 side buffer V1h: 16B rows, XOR layout conflict-free for
//      write pattern h=4l+j and read pattern h=l+32m ----
__device__ __forceinline__ int off16f(int h)   // float offset of 16B row
{
    return ((h & 3) * 32 + ((h >> 2) ^ (2 * (h & 3)))) * 4;
}

// Forward matvec (smem input), 8 batches as 4 f32x2 pairs.
__device__ __forceinline__ void fwd2(const float* __restrict__ Wt,
                                     const float* __restrict__ biasg,
                                     const float* __restrict__ inq,
                                     ull z[4][4], int l)
{
    float4 bb = *(const float4*)&biasg[4*l];   // global, L1 hit
    float bj[4] = {bb.x, bb.y, bb.z, bb.w};
#pragma unroll
    for (int j = 0; j < 4; ++j) {
        ull b2 = pack2(bj[j], bj[j]);
#pragma unroll
        for (int pp = 0; pp < 4; ++pp) z[j][pp] = b2;
    }

#pragma unroll 4
    for (int k = 0; k < HID; ++k) {
        float4 w4 = *(const float4*)&Wt[k*PAD + 4*l];   // 128B contiguous
        const float* rp = inq + physrow(k)*8;
        int b = cswap(k);
        ulonglong2 xa = *(const ulonglong2*)(rp + 4*b);
        ulonglong2 xb = *(const ulonglong2*)(rp + 4*(b^1));
        ull x[4] = {xa.x, xa.y, xb.x, xb.y};
        float wj[4] = {w4.x, w4.y, w4.z, w4.w};
#pragma unroll
        for (int j = 0; j < 4; ++j) {
            ull w2 = pack2(wj[j], wj[j]);
#pragma unroll
            for (int pp = 0; pp < 4; ++pp)
                z[j][pp] = ffma2(w2, x[pp], z[j][pp]);
        }
    }
}

// Input-layer forward (K=12), x pairs delivered by warp shuffles.
__device__ __forceinline__ void fwd2x(const float* __restrict__ Wt,
                                      const float* __restrict__ biasg,
                                      ull ua, ull ub, ull z[4][4], int l)
{
    float4 bb = *(const float4*)&biasg[4*l];
    float bj[4] = {bb.x, bb.y, bb.z, bb.w};
#pragma unroll
    for (int j = 0; j < 4; ++j) {
        ull b2 = pack2(bj[j], bj[j]);
#pragma unroll
        for (int pp = 0; pp < 4; ++pp) z[j][pp] = b2;
    }

#pragma unroll
    for (int k = 0; k < NS; ++k) {
        ull x[4];
#pragma unroll
        for (int pp = 0; pp < 4; ++pp)
            x[pp] = (k < 8) ? shflx(ua, 4*k + pp) : shflx(ub, 4*(k-8) + pp);
        float4 w4 = *(const float4*)&Wt[k*PAD + 4*l];
        float wj[4] = {w4.x, w4.y, w4.z, w4.w};
#pragma unroll
        for (int j = 0; j < 4; ++j) {
            ull w2 = pack2(wj[j], wj[j]);
#pragma unroll
            for (int pp = 0; pp < 4; ++pp)
                z[j][pp] = ffma2(w2, x[pp], z[j][pp]);
        }
    }
}

// Backward vecmat: r[m][pp] = sum_h g[h][pp] * Wt[(l+32m)][h]
__device__ __forceinline__ void bwd2(const float* __restrict__ Wt,
                                     const float* __restrict__ gin,
                                     ull r[4][4], int l)
{
#pragma unroll
    for (int m = 0; m < 4; ++m)
#pragma unroll
        for (int pp = 0; pp < 4; ++pp) r[m][pp] = 0ull;

#pragma unroll 2
    for (int c = 0; c < 32; ++c) {          // chunks of 4 h-rows
        int perm = c & 3, b = (c ^ (c >> 2)) & 1;
        ull g[4][4];
#pragma unroll
        for (int sg = 0; sg < 4; ++sg) {
            const float* rp = gin + (4*c + (sg ^ perm))*8;   // = physrow(4c+sg)
            ulonglong2 ga = *(const ulonglong2*)(rp + 4*b);
            ulonglong2 gb = *(const ulonglong2*)(rp + 4*(b^1));
            g[sg][0] = ga.x; g[sg][1] = ga.y; g[sg][2] = gb.x; g[sg][3] = gb.y;
        }
#pragma unroll
        for (int m = 0; m < 4; ++m) {
            float4 w4 = *(const float4*)&Wt[(l + 32*m)*PAD + 4*c]; // conflict-free
            float wm[4] = {w4.x, w4.y, w4.z, w4.w};
#pragma unroll
            for (int sg = 0; sg < 4; ++sg) {
                ull w2 = pack2(wm[sg], wm[sg]);
#pragma unroll
                for (int pp = 0; pp < 4; ++pp)
                    r[m][pp] = ffma2(w2, g[sg][pp], r[m][pp]);
            }
        }
    }
}

__global__ __launch_bounds__(THREADS, 1)
void mlp_kernel(const float* __restrict__ state,
                const float* __restrict__ safe_m, const float* __restrict__ safe_l,
                const float* __restrict__ W0, const float* __restrict__ b0,
                const float* __restrict__ W1, const float* __restrict__ b1,
                const float* __restrict__ W2, const float* __restrict__ b2,
                float* __restrict__ out, int nb)
{
    extern __shared__ float s[];
    int tid = threadIdx.x;

    // ---- stage weights into SMEM (transposed, PAD-pitched) ----
    for (int i = tid; i < HID*HID; i += THREADS) {
        int h = i >> 7, k = i & 127;
        s[OW1 + k*PAD + h] = W1[i];
        s[OW2 + k*PAD + h] = W2[i];
    }
    for (int i = tid; i < HID*NS; i += THREADS) {
        int h = i / NS, k = i - h*NS;
        s[OW0 + k*PAD + h] = W0[i];
    }
    if (tid < NS) {
        float m = safe_m[tid], lo = safe_l[tid];
        s[OCEN + tid] = 0.5f * (m + lo);
        s[OINV + tid] = 2.0f / (m - lo);
    }
    __syncthreads();

    int w = tid >> 5, l = tid & 31;
    float* BigA = s + OWARP + w*WSTRIDE;     // [128][8] fp32, swizzled: V0 -> V1 -> g2 -> g1 -> g0
    float* V1h  = BigA + 1024;               // [128] 16B fp16 rows, XOR layout

    int gw = blockIdx.x + GRID * w;          // warp-major: one task per warp
    int quads = (nb + NB - 1) / NB;
    if (gw < quads) {
        int base = gw * NB;

        // ---- A: load + normalize inputs into 2 register pairs per lane ----
        ull ua, ub;
        {
            int p0 = 2*(l & 3);
            int ka = l >> 2;                  // 0..7
            int kb = 8 + ((l >> 2) & 3);      // 8..11
            int i0 = base + p0, i1 = base + p0 + 1;
            float a0 = (i0 < nb) ? state[i0*NS + ka] : 0.f;
            float a1 = (i1 < nb) ? state[i1*NS + ka] : 0.f;
            float c0 = (i0 < nb) ? state[i0*NS + kb] : 0.f;
            float c1 = (i1 < nb) ? state[i1*NS + kb] : 0.f;
            float ca = s[OCEN + ka], ia = s[OINV + ka];
            float cb = s[OCEN + kb], ib = s[OINV + kb];
            ua = pack2((a0 - ca)*ia, (a1 - ca)*ia);
            ub = pack2((c0 - cb)*ib, (c1 - cb)*ib);
        }

        ull z[4][4];
        float t[8];

        // ---- B: input layer (K=12, shfl x) + tanh -> V0 (BigA) ----
        fwd2x(s + OW0, b0, ua, ub, z, l);
#pragma unroll
        for (int j = 0; j < 4; ++j) {
#pragma unroll
            for (int pp = 0; pp < 4; ++pp) unpack2(z[j][pp], t[2*pp], t[2*pp+1]);
#pragma unroll
            for (int p = 0; p < 8; ++p) t[p] = ftanh(t[p]);
            store8(BigA, 4*l + j, t);
        }
        __syncwarp();

        // ---- C: layer 1 + tanh -> V1 (BigA, in place) + fp16 copy (V1h) ----
        fwd2(s + OW1, b1, BigA, z, l);
        __syncwarp();                        // all reads of V0 done before overwrite
#pragma unroll
        for (int j = 0; j < 4; ++j) {
#pragma unroll
            for (int pp = 0; pp < 4; ++pp) unpack2(z[j][pp], t[2*pp], t[2*pp+1]);
#pragma unroll
            for (int p = 0; p < 8; ++p) t[p] = ftanh(t[p]);
            store8(BigA, 4*l + j, t);
            __half2 h0 = __floats2half2_rn(t[0], t[1]);
            __half2 h1 = __floats2half2_rn(t[2], t[3]);
            __half2 h2 = __floats2half2_rn(t[4], t[5]);
            __half2 h3 = __floats2half2_rn(t[6], t[7]);
            uint4 u;
            u.x = *(unsigned*)&h0; u.y = *(unsigned*)&h1;
            u.z = *(unsigned*)&h2; u.w = *(unsigned*)&h3;
            *(uint4*)&V1h[off16f(4*l + j)] = u;
        }
        __syncwarp();

        // ---- D: layer 2 + tanh; vout = R3.V2 (output now); g2 -> BigA ----
        fwd2(s + OW2, b2, BigA, z, l);
        __syncwarp();                        // V1 reads complete
        {
            ull vo[4] = {0ull, 0ull, 0ull, 0ull};
            float4 r4 = *(const float4*)&g_R3[4*l];
            float rj[4] = {r4.x, r4.y, r4.z, r4.w};
#pragma unroll
            for (int j = 0; j < 4; ++j) {
                ull rj2 = pack2(rj[j], rj[j]);
#pragma unroll
                for (int pp = 0; pp < 4; ++pp) unpack2(z[j][pp], t[2*pp], t[2*pp+1]);
#pragma unroll
                for (int p = 0; p < 8; ++p) t[p] = ftanh(t[p]);
#pragma unroll
                for (int pp = 0; pp < 4; ++pp)
                    vo[pp] = ffma2(rj2, pack2(t[2*pp], t[2*pp+1]), vo[pp]);
                float gq[8];
#pragma unroll
                for (int p = 0; p < 8; ++p) gq[p] = rj[j] * (1.f - t[p]*t[p]);
                store8(BigA, 4*l + j, gq);
            }
            float vout[8];
#pragma unroll
            for (int pp = 0; pp < 4; ++pp) unpack2(vo[pp], vout[2*pp], vout[2*pp+1]);
#pragma unroll
            for (int p = 0; p < 8; ++p) {
                float v = vout[p];
#pragma unroll
                for (int off = 16; off > 0; off >>= 1)
                    v += __shfl_xor_sync(0xffffffffu, v, off);
                vout[p] = v;
            }
            if (l == 0) {
                float c3 = g_c3;
#pragma unroll
                for (int p = 0; p < 8; ++p)
                    if (base + p < nb) out[(base + p)*13] = vout[p] + c3;
            }
        }
        __syncwarp();

        ull r[4][4];

        // ---- E: r = g2.W2 ; s1 from fp16 copy; g1 -> BigA ----
        bwd2(s + OW2, BigA, r, l);
        __syncwarp();
#pragma unroll
        for (int m = 0; m < 4; ++m) {
            uint4 u = *(const uint4*)&V1h[off16f(l + 32*m)];
            float2 f0 = __half22float2(*(__half2*)&u.x);
            float2 f1 = __half22float2(*(__half2*)&u.y);
            float2 f2 = __half22float2(*(__half2*)&u.z);
            float2 f3 = __half22float2(*(__half2*)&u.w);
            float vp[8] = {f0.x, f0.y, f1.x, f1.y, f2.x, f2.y, f3.x, f3.y};
            float gq[8];
#pragma unroll
            for (int pp = 0; pp < 4; ++pp) {
                float r0, r1; unpack2(r[m][pp], r0, r1);
                gq[2*pp]   = r0 * (1.f - vp[2*pp]*vp[2*pp]);
                gq[2*pp+1] = r1 * (1.f - vp[2*pp+1]*vp[2*pp+1]);
            }
            store8(BigA, l + 32*m, gq);
        }
        __syncwarp();

        // ---- F: s0 recomputed from register x (shfl); r = g1.W1 ; g0 -> BigA ----
        float s0[4][8];
        {
            ull z0[4][4];
#pragma unroll
            for (int m = 0; m < 4; ++m) {
                float bm = b0[l + 32*m];
                ull b2 = pack2(bm, bm);
#pragma unroll
                for (int pp = 0; pp < 4; ++pp) z0[m][pp] = b2;
            }
#pragma unroll
            for (int k = 0; k < NS; ++k) {
                ull x[4];
#pragma unroll
                for (int pp = 0; pp < 4; ++pp)
                    x[pp] = (k < 8) ? shflx(ua, 4*k + pp) : shflx(ub, 4*(k-8) + pp);
#pragma unroll
                for (int m = 0; m < 4; ++m) {
                    float wv = s[OW0 + k*PAD + l + 32*m];
                    ull w2 = pack2(wv, wv);
#pragma unroll
                    for (int pp = 0; pp < 4; ++pp)
                        z0[m][pp] = ffma2(w2, x[pp], z0[m][pp]);
                }
            }
#pragma unroll
            for (int m = 0; m < 4; ++m)
#pragma unroll
                for (int pp = 0; pp < 4; ++pp) {
                    float a, b; unpack2(z0[m][pp], a, b);
                    a = ftanh(a); b = ftanh(b);
                    s0[m][2*pp]   = 1.f - a*a;
                    s0[m][2*pp+1] = 1.f - b*b;
                }
        }
        bwd2(s + OW1, BigA, r, l);
        __syncwarp();
#pragma unroll
        for (int m = 0; m < 4; ++m) {
            float gq[8];
#pragma unroll
            for (int pp = 0; pp < 4; ++pp) {
                float r0, r1; unpack2(r[m][pp], r0, r1);
                gq[2*pp]   = r0 * s0[m][2*pp];
                gq[2*pp+1] = r1 * s0[m][2*pp+1];
            }
            store8(BigA, l + 32*m, gq);
        }
        __syncwarp();

        // ---- final: J[k][p] = (sum_h g0[h][p] * W0t[k][h]) * inv[k] ----
        {
            int p  = l & 7;
            int k0 = l >> 3;                 // k = k0 + 4c, c in 0..2
            int psel = p >> 2, pw = p & 3;
            float acc[3] = {0.f, 0.f, 0.f};
#pragma unroll 2
            for (int i = 0; i < 32; ++i) {   // h = 4i..4i+3
                float4 w0 = *(const float4*)&s[OW0 + (k0    )*PAD + 4*i];
                float4 w1 = *(const float4*)&s[OW0 + (k0 + 4)*PAD + 4*i];
                float4 w2 = *(const float4*)&s[OW0 + (k0 + 8)*PAD + 4*i];
                float gv[4];
#pragma unroll
                for (int d = 0; d < 4; ++d) {
                    int h = 4*i + d;
                    gv[d] = BigA[physrow(h)*8 + 4*(psel ^ cswap(h)) + pw];
                }
                acc[0] = fmaf(w0.x, gv[0], acc[0]); acc[0] = fmaf(w0.y, gv[1], acc[0]);
                acc[0] = fmaf(w0.z, gv[2], acc[0]); acc[0] = fmaf(w0.w, gv[3], acc[0]);
                acc[1] = fmaf(w1.x, gv[0], acc[1]); acc[1] = fmaf(w1.y, gv[1], acc[1]);
                acc[1] = fmaf(w1.z, gv[2], acc[1]); acc[1] = fmaf(w1.w, gv[3], acc[1]);
                acc[2] = fmaf(w2.x, gv[0], acc[2]); acc[2] = fmaf(w2.y, gv[1], acc[2]);
                acc[2] = fmaf(w2.z, gv[2], acc[2]); acc[2] = fmaf(w2.w, gv[3], acc[2]);
            }
            if (base + p < nb) {
#pragma unroll
                for (int c = 0; c < 3; ++c) {
                    int k = k0 + 4*c;
                    out[(base + p)*13 + 1 + k] = acc[c] * s[OINV + k];
                }
            }
        }
    }
}

extern "C" void kernel_launch(void* const* d_in, const int* in_sizes, int n_in,
                              void* d_out, int out_size)
{
    const float* state  = (const float*)d_in[0];
    const float* safe_m = (const float*)d_in[1];
    const float* safe_l = (const float*)d_in[2];
    const float* W0     = (const float*)d_in[3];
    const float* b0     = (const float*)d_in[4];
    const float* W1     = (const float*)d_in[5];
    const float* b1     = (const float*)d_in[6];
    const float* W2     = (const float*)d_in[7];
    const float* b2     = (const float*)d_in[8];
    const float* W3     = (const float*)d_in[9];
    const float* b3     = (const float*)d_in[10];
    const float* Wout   = (const float*)d_in[11];
    const float* bout   = (const float*)d_in[12];
    float* out = (float*)d_out;

    int nb = in_sizes[0] / NS;

    cudaFuncSetAttribute(mlp_kernel, cudaFuncAttributeMaxDynamicSharedMemorySize,
                         SMEM_FLOATS * (int)sizeof(float));

    init_kernel<<<1, HID>>>(W3, b3, Wout, bout);
    mlp_kernel<<<GRID, THREADS, SMEM_FLOATS * sizeof(float)>>>(
        state, safe_m, safe_l, W0, b0, W1, b1, W2, b2, out, nb);
}